// round 1
// baseline (speedup 1.0000x reference)
#include <cuda_runtime.h>
#include <cstdint>

// Problem constants
#define BB 64
#define TT 1024
#define KK 256
#define HALF 128          // K / 2 columns per CTA in the 2-CTA cluster
#define CHUNK 32
#define NCHUNK 32         // TT / CHUNK

#define NEG_INF __int_as_float(0xff800000)

// ---------------- scratch (static __device__, no allocation allowed) -------
__device__ unsigned char g_bp[(TT - 1) * BB * KK];            // backpointers ~16.7MB
__device__ unsigned char g_path[BB * TT * KK];                // per-chunk hypothetical paths ~16.7MB
__device__ unsigned char g_bmap[(NCHUNK - 1) * BB * KK];      // chunk boundary maps
__device__ float         g_final[BB * KK];                    // final Viterbi scores
__device__ int           g_lasttag[BB];
__device__ int           g_sel[(NCHUNK - 1) * BB];            // selected end-tag per chunk

// ---------------- cluster helpers ------------------------------------------
__device__ __forceinline__ void cluster_sync_all() {
    asm volatile("barrier.cluster.arrive.aligned;" ::: "memory");
    asm volatile("barrier.cluster.wait.aligned;" ::: "memory");
}

__device__ __forceinline__ void dsmem_store_f32(float* localPtr, unsigned peerRank, float v) {
    uint32_t laddr = (uint32_t)__cvta_generic_to_shared(localPtr);
    uint32_t raddr;
    asm volatile("mapa.shared::cluster.u32 %0, %1, %2;"
                 : "=r"(raddr) : "r"(laddr), "r"(peerRank));
    asm volatile("st.shared::cluster.f32 [%0], %1;"
                 :: "r"(raddr), "f"(v) : "memory");
}

// ---------------- forward kernel -------------------------------------------
// 2 CTAs per batch (cluster), each CTA owns trans columns [rank*128, rank*128+128).
// 256 threads = 8 i-groups (warps) x 32 j-quads. Thread (ti,tj) reduces
// i in [32*ti, 32*ti+32) for j_local in [4*tj, 4*tj+4).
// SMEM: trans half 128KB | state double buffer 2x256 | partials 8x128 (v,i)
extern __shared__ __align__(16) char smem_raw[];

__global__ void __cluster_dims__(2, 1, 1) __launch_bounds__(256, 1)
fwd_kernel(const float* __restrict__ em, const float* __restrict__ trans)
{
    float* transS = (float*)smem_raw;                 // KK*HALF floats
    float* st0    = transS + KK * HALF;               // KK
    float* st1    = st0 + KK;                         // KK
    float* redv   = st1 + KK;                         // 8*HALF
    int*   redi   = (int*)(redv + 8 * HALF);          // 8*HALF

    const int bid  = blockIdx.x;
    const int b    = bid >> 1;
    const int rank = bid & 1;
    const int tid  = threadIdx.x;
    const int tj   = tid & 31;
    const int ti   = tid >> 5;

    // Load this CTA's transition half into SMEM (column block rank*128..+128)
    for (int idx = tid; idx < (KK * HALF) / 4; idx += 256) {
        int i  = idx >> 5;       // 32 float4 per row
        int c4 = idx & 31;
        float4 v = ((const float4*)(trans + i * KK + rank * HALF))[c4];
        ((float4*)(transS + i * HALF))[c4] = v;
    }
    // Initial state = emissions[b, 0, :]
    for (int j = tid; j < KK; j += 256)
        st0[j] = em[(b * TT + 0) * KK + j];
    __syncthreads();
    cluster_sync_all();

    for (int t = 1; t < TT; ++t) {
        float* cur = (t & 1) ? st0 : st1;
        float* nxt = (t & 1) ? st1 : st0;

        // Prefetch this step's emission (consumed ~1200 cycles later)
        float emv = 0.0f;
        if (tid < HALF)
            emv = __ldg(&em[(b * TT + t) * KK + rank * HALF + tid]);

        float a0 = NEG_INF, a1 = NEG_INF, a2 = NEG_INF, a3 = NEG_INF;
        int   i0 = 0, i1 = 0, i2 = 0, i3 = 0;
        const int ibase = ti * 32;

        #pragma unroll 8
        for (int k = 0; k < 32; ++k) {
            int i = ibase + k;
            float sv = cur[i];                                   // LDS broadcast
            float4 tr = ((const float4*)(transS + i * HALF))[tj]; // LDS.128
            float s;
            s = sv + tr.x; if (s > a0) { a0 = s; i0 = i; }
            s = sv + tr.y; if (s > a1) { a1 = s; i1 = i; }
            s = sv + tr.z; if (s > a2) { a2 = s; i2 = i; }
            s = sv + tr.w; if (s > a3) { a3 = s; i3 = i; }
        }

        ((float4*)(redv + ti * HALF))[tj] = make_float4(a0, a1, a2, a3);
        ((int4*)  (redi + ti * HALF))[tj] = make_int4(i0, i1, i2, i3);
        __syncthreads();

        if (tid < HALF) {
            float v  = redv[tid];
            int   bi = redi[tid];
            #pragma unroll
            for (int g = 1; g < 8; ++g) {
                float nv = redv[g * HALF + tid];
                int   ni = redi[g * HALF + tid];
                bool better = nv > v;            // strict > keeps lowest i (first argmax)
                v  = better ? nv : v;
                bi = better ? ni : bi;
            }
            int jf = rank * HALF + tid;
            float ns = v + emv;
            nxt[jf] = ns;
            dsmem_store_f32(nxt + jf, rank ^ 1u, ns);
            g_bp[((t - 1) * BB + b) * KK + jf] = (unsigned char)bi;
        }
        cluster_sync_all();  // release own-half writes, acquire peer half
    }

    // t = TT-1 (odd) wrote into st1 -> final scores
    if (tid < HALF) {
        int jf = rank * HALF + tid;
        g_final[b * KK + jf] = st1[jf];
    }
}

// ---------------- last tag: argmax over final state (first-index ties) -----
__global__ void lasttag_kernel()
{
    int b = blockIdx.x;
    int lane = threadIdx.x;
    float v = NEG_INF;
    int bi = KK;  // larger than any real index so ties resolve correctly
    #pragma unroll
    for (int g = 0; g < 8; ++g) {
        int j = g * 32 + lane;
        float nv = g_final[b * KK + j];
        if (nv > v || (nv == v && j < bi)) { v = nv; bi = j; }
    }
    #pragma unroll
    for (int off = 16; off; off >>= 1) {
        float ov = __shfl_xor_sync(0xffffffffu, v, off);
        int   oi = __shfl_xor_sync(0xffffffffu, bi, off);
        if (ov > v || (ov == v && oi < bi)) { v = ov; bi = oi; }
    }
    if (lane == 0) g_lasttag[b] = bi;
}

// ---------------- phase 1: chase all hypothetical end-tags per chunk -------
// One CTA per (chunk c, batch b); thread j chases assuming tags[(c+1)*CHUNK]=j.
__global__ void phase1_kernel()
{
    int cb = blockIdx.x;            // (NCHUNK-1)*BB blocks
    int c  = cb / BB;               // 0..NCHUNK-2
    int b  = cb % BB;
    int j  = threadIdx.x;           // 256
    int cur = j;
    int tend = (c + 1) * CHUNK;
    for (int t = tend - 1; t >= c * CHUNK; --t) {
        cur = g_bp[(t * BB + b) * KK + cur];
        g_path[(b * TT + t) * KK + j] = (unsigned char)cur;
    }
    g_bmap[(c * BB + b) * KK + j] = (unsigned char)cur;
}

// ---------------- phase 2: serial chase of last chunk + boundary maps ------
__global__ void phase2_kernel(float* __restrict__ out)
{
    int b = threadIdx.x;
    if (b >= BB) return;
    int cur = g_lasttag[b];
    out[b * TT + (TT - 1)] = (float)cur;
    for (int t = TT - 2; t >= (NCHUNK - 1) * CHUNK; --t) {
        cur = g_bp[(t * BB + b) * KK + cur];
        out[b * TT + t] = (float)cur;
    }
    int anchor = cur;               // = tags[(NCHUNK-1)*CHUNK]
    for (int c = NCHUNK - 2; c >= 0; --c) {
        g_sel[c * BB + b] = anchor; // end-tag for chunk c = tags[(c+1)*CHUNK]
        anchor = g_bmap[(c * BB + b) * KK + anchor];
    }
}

// ---------------- phase 3: gather decoded tags from path table -------------
__global__ void phase3_kernel(float* __restrict__ out)
{
    int idx = blockIdx.x * blockDim.x + threadIdx.x;
    const int nT = (NCHUNK - 1) * CHUNK;   // 992
    if (idx >= BB * nT) return;
    int b = idx / nT;
    int t = idx % nT;
    int c = t / CHUNK;
    int s = g_sel[c * BB + b];
    out[b * TT + t] = (float)g_path[(b * TT + t) * KK + s];
}

// ---------------- launch ----------------------------------------------------
extern "C" void kernel_launch(void* const* d_in, const int* in_sizes, int n_in,
                              void* d_out, int out_size)
{
    const float* em    = (const float*)d_in[0];  // [B, T, K] fp32
    const float* trans = (const float*)d_in[1];  // [K, K] fp32
    float* out = (float*)d_out;                  // [B, T] fp32

    const size_t smem_bytes =
        (size_t)(KK * HALF + 2 * KK + 8 * HALF) * sizeof(float) +
        (size_t)(8 * HALF) * sizeof(int);        // 141312 bytes

    static bool attr_done = false;
    // Setting the attribute is idempotent; call unconditionally to stay
    // deterministic and capture-safe (not a stream op).
    (void)attr_done;
    cudaFuncSetAttribute(fwd_kernel,
                         cudaFuncAttributeMaxDynamicSharedMemorySize,
                         (int)smem_bytes);

    fwd_kernel<<<2 * BB, 256, smem_bytes>>>(em, trans);
    lasttag_kernel<<<BB, 32>>>();
    phase1_kernel<<<(NCHUNK - 1) * BB, 256>>>();
    phase2_kernel<<<1, 64>>>(out);
    {
        int total = BB * (NCHUNK - 1) * CHUNK;
        phase3_kernel<<<(total + 255) / 256, 256>>>(out);
    }
}